// round 1
// baseline (speedup 1.0000x reference)
#include <cuda_runtime.h>
#include <math.h>

#define N_PTS 16384
#define DIM 256
#define HEADS 8
#define HD 32
#define KNN 20
#define MLP_HID 1024
#define SEGS 8
#define SEGLEN (N_PTS / SEGS)   // 2048
#define LISTLEN 21              // keep 21 so self can be dropped at merge
#define SCALE 0.17677669529663687f  // 32^-0.5

// ---------------- scratch (device globals; no allocation allowed) ----------
__device__ float g_h[N_PTS * DIM];       // LN1 out, later reused for LN2 out
__device__ float g_q[N_PTS * DIM];
__device__ float g_k[N_PTS * DIM];
__device__ float g_v[N_PTS * DIM];
__device__ float g_attn[N_PTS * DIM];
__device__ float g_x1[N_PTS * DIM];      // residual-1 result
__device__ float g_hid[N_PTS * MLP_HID];
__device__ int   g_knn[N_PTS * KNN];
__device__ float g_pd[N_PTS * SEGS * LISTLEN];
__device__ int   g_pi[N_PTS * SEGS * LISTLEN];

// ---------------- kNN pass 1: per-segment top-21 ---------------------------
__global__ __launch_bounds__(256) void knn_part_kernel(const float* __restrict__ pos) {
    __shared__ float sx[SEGLEN], sy[SEGLEN], sz[SEGLEN];
    const int seg  = blockIdx.y;
    const int base = seg * SEGLEN;
    for (int t = threadIdx.x; t < SEGLEN; t += blockDim.x) {
        sx[t] = pos[(base + t) * 3 + 0];
        sy[t] = pos[(base + t) * 3 + 1];
        sz[t] = pos[(base + t) * 3 + 2];
    }
    __syncthreads();

    const int qi = blockIdx.x * blockDim.x + threadIdx.x;
    const float qx = pos[qi * 3 + 0];
    const float qy = pos[qi * 3 + 1];
    const float qz = pos[qi * 3 + 2];

    float bd[LISTLEN];
    int   bi[LISTLEN];
#pragma unroll
    for (int s = 0; s < LISTLEN; s++) { bd[s] = 3.0e38f; bi[s] = -1; }

#pragma unroll 4
    for (int t = 0; t < SEGLEN; t++) {
        float dx = qx - sx[t];
        float dy = qy - sy[t];
        float dz = qz - sz[t];
        float d = dx * dx + dy * dy + dz * dz;
        if (d < bd[LISTLEN - 1]) {
            bd[LISTLEN - 1] = d; bi[LISTLEN - 1] = base + t;
#pragma unroll
            for (int s = LISTLEN - 1; s > 0; --s) {
                if (bd[s] < bd[s - 1]) {
                    float td = bd[s]; bd[s] = bd[s - 1]; bd[s - 1] = td;
                    int   ti = bi[s]; bi[s] = bi[s - 1]; bi[s - 1] = ti;
                }
            }
        }
    }
    size_t o = ((size_t)qi * SEGS + seg) * LISTLEN;
#pragma unroll
    for (int s = 0; s < LISTLEN; s++) { g_pd[o + s] = bd[s]; g_pi[o + s] = bi[s]; }
}

// ---------------- kNN pass 2: merge segments, drop self --------------------
__global__ __launch_bounds__(256) void knn_merge_kernel() {
    const int qi = blockIdx.x * blockDim.x + threadIdx.x;
    float bd[KNN];
    int   bi[KNN];
#pragma unroll
    for (int s = 0; s < KNN; s++) { bd[s] = 3.0e38f; bi[s] = -1; }
    size_t o = (size_t)qi * SEGS * LISTLEN;
    for (int t = 0; t < SEGS * LISTLEN; t++) {
        float d = g_pd[o + t];
        int   j = g_pi[o + t];
        if (j != qi && d < bd[KNN - 1]) {
            bd[KNN - 1] = d; bi[KNN - 1] = j;
#pragma unroll
            for (int s = KNN - 1; s > 0; --s) {
                if (bd[s] < bd[s - 1]) {
                    float td = bd[s]; bd[s] = bd[s - 1]; bd[s - 1] = td;
                    int   ti = bi[s]; bi[s] = bi[s - 1]; bi[s - 1] = ti;
                }
            }
        }
    }
#pragma unroll
    for (int s = 0; s < KNN; s++) g_knn[qi * KNN + s] = bi[s];
}

// ---------------- LayerNorm: one warp per row ------------------------------
__global__ __launch_bounds__(256) void ln_kernel(const float* __restrict__ x,
                                                 const float* __restrict__ w,
                                                 const float* __restrict__ b,
                                                 float* __restrict__ out) {
    const int warp = threadIdx.x >> 5;
    const int lane = threadIdx.x & 31;
    const int n = blockIdx.x * 8 + warp;
    const float4* xr = (const float4*)(x + (size_t)n * DIM + lane * 8);
    float4 a0 = xr[0], a1 = xr[1];
    float s1 = a0.x + a0.y + a0.z + a0.w + a1.x + a1.y + a1.z + a1.w;
    float s2 = a0.x * a0.x + a0.y * a0.y + a0.z * a0.z + a0.w * a0.w +
               a1.x * a1.x + a1.y * a1.y + a1.z * a1.z + a1.w * a1.w;
#pragma unroll
    for (int off = 16; off > 0; off >>= 1) {
        s1 += __shfl_xor_sync(0xffffffffu, s1, off);
        s2 += __shfl_xor_sync(0xffffffffu, s2, off);
    }
    float m = s1 * (1.0f / DIM);
    float var = s2 * (1.0f / DIM) - m * m;
    float r = rsqrtf(var + 1e-5f);
    const float4* wr = (const float4*)(w + lane * 8);
    const float4* br = (const float4*)(b + lane * 8);
    float4 w0 = wr[0], w1 = wr[1], b0 = br[0], b1 = br[1];
    float4 o0, o1;
    o0.x = (a0.x - m) * r * w0.x + b0.x;
    o0.y = (a0.y - m) * r * w0.y + b0.y;
    o0.z = (a0.z - m) * r * w0.z + b0.z;
    o0.w = (a0.w - m) * r * w0.w + b0.w;
    o1.x = (a1.x - m) * r * w1.x + b1.x;
    o1.y = (a1.y - m) * r * w1.y + b1.y;
    o1.z = (a1.z - m) * r * w1.z + b1.z;
    o1.w = (a1.w - m) * r * w1.w + b1.w;
    float4* orow = (float4*)(out + (size_t)n * DIM + lane * 8);
    orow[0] = o0; orow[1] = o1;
}

// ---------------- generic SGEMM: C = act(A * B^T + bias) [+ R] -------------
// A [M,Kd] row-major, B [Nn,Kd] row-major (weight layout), C [M,Nn]
#define BM 64
#define BN 64
#define BKK 16

template <int ACT, int RES>
__global__ __launch_bounds__(256) void gemm_kernel(const float* __restrict__ A,
                                                   const float* __restrict__ B,
                                                   const float* __restrict__ bias,
                                                   const float* __restrict__ R,
                                                   float* __restrict__ C,
                                                   int M, int Nn, int Kd) {
    __shared__ float As[BKK][BM + 4];
    __shared__ float Bs[BKK][BN + 4];
    const int tid = threadIdx.x;
    const int n0 = blockIdx.x * BN;
    const int m0 = blockIdx.y * BM;
    const int lrow = tid >> 2;
    const int lcol = (tid & 3) * 4;
    const int ty = tid >> 4;
    const int tx = tid & 15;
    float acc[4][4] = {};
    for (int k0 = 0; k0 < Kd; k0 += BKK) {
        float4 av = *(const float4*)(A + (size_t)(m0 + lrow) * Kd + k0 + lcol);
        float4 bv = *(const float4*)(B + (size_t)(n0 + lrow) * Kd + k0 + lcol);
        As[lcol + 0][lrow] = av.x; As[lcol + 1][lrow] = av.y;
        As[lcol + 2][lrow] = av.z; As[lcol + 3][lrow] = av.w;
        Bs[lcol + 0][lrow] = bv.x; Bs[lcol + 1][lrow] = bv.y;
        Bs[lcol + 2][lrow] = bv.z; Bs[lcol + 3][lrow] = bv.w;
        __syncthreads();
#pragma unroll
        for (int kk = 0; kk < BKK; kk++) {
            float4 a = *(const float4*)&As[kk][ty * 4];
            float4 b = *(const float4*)&Bs[kk][tx * 4];
            acc[0][0] += a.x * b.x; acc[0][1] += a.x * b.y; acc[0][2] += a.x * b.z; acc[0][3] += a.x * b.w;
            acc[1][0] += a.y * b.x; acc[1][1] += a.y * b.y; acc[1][2] += a.y * b.z; acc[1][3] += a.y * b.w;
            acc[2][0] += a.z * b.x; acc[2][1] += a.z * b.y; acc[2][2] += a.z * b.z; acc[2][3] += a.z * b.w;
            acc[3][0] += a.w * b.x; acc[3][1] += a.w * b.y; acc[3][2] += a.w * b.z; acc[3][3] += a.w * b.w;
        }
        __syncthreads();
    }
    float4 bb = *(const float4*)(bias + n0 + tx * 4);
#pragma unroll
    for (int i = 0; i < 4; i++) {
        const int m = m0 + ty * 4 + i;
        float4 c;
        c.x = acc[i][0] + bb.x;
        c.y = acc[i][1] + bb.y;
        c.z = acc[i][2] + bb.z;
        c.w = acc[i][3] + bb.w;
        if (ACT == 1) {  // exact GELU
            c.x = 0.5f * c.x * (1.0f + erff(c.x * 0.70710678118654752f));
            c.y = 0.5f * c.y * (1.0f + erff(c.y * 0.70710678118654752f));
            c.z = 0.5f * c.z * (1.0f + erff(c.z * 0.70710678118654752f));
            c.w = 0.5f * c.w * (1.0f + erff(c.w * 0.70710678118654752f));
        }
        if (RES) {
            float4 r = *(const float4*)(R + (size_t)m * Nn + n0 + tx * 4);
            c.x += r.x; c.y += r.y; c.z += r.z; c.w += r.w;
        }
        *(float4*)(C + (size_t)m * Nn + n0 + tx * 4) = c;
    }
}

// ---------------- local attention: one warp per point ----------------------
// lane l handles feature elems [8l, 8l+8) => head = l/4, 4 lanes per head
__global__ __launch_bounds__(256) void attn_kernel(const float* __restrict__ q,
                                                   const float* __restrict__ k,
                                                   const float* __restrict__ v,
                                                   const int* __restrict__ knn,
                                                   float* __restrict__ out) {
    const int warp = threadIdx.x >> 5;
    const int lane = threadIdx.x & 31;
    const int n = blockIdx.x * 8 + warp;
    const float4* qr = (const float4*)(q + (size_t)n * DIM + lane * 8);
    float4 q0 = qr[0], q1 = qr[1];

    int idx[KNN];
#pragma unroll
    for (int j = 0; j < KNN; j++) idx[j] = knn[n * KNN + j];

    float w[KNN];
#pragma unroll
    for (int j = 0; j < KNN; j++) {
        const float4* kr = (const float4*)(k + (size_t)idx[j] * DIM + lane * 8);
        float4 k0 = kr[0], k1 = kr[1];
        float s = q0.x * k0.x + q0.y * k0.y + q0.z * k0.z + q0.w * k0.w +
                  q1.x * k1.x + q1.y * k1.y + q1.z * k1.z + q1.w * k1.w;
        s += __shfl_xor_sync(0xffffffffu, s, 1);
        s += __shfl_xor_sync(0xffffffffu, s, 2);
        w[j] = s * SCALE;
    }
    float mx = -3.0e38f;
#pragma unroll
    for (int j = 0; j < KNN; j++) mx = fmaxf(mx, w[j]);
    float sum = 0.0f;
#pragma unroll
    for (int j = 0; j < KNN; j++) { w[j] = expf(w[j] - mx); sum += w[j]; }
    const float inv = 1.0f / sum;

    float4 o0 = {0, 0, 0, 0}, o1 = {0, 0, 0, 0};
#pragma unroll
    for (int j = 0; j < KNN; j++) {
        const float wj = w[j] * inv;
        const float4* vr = (const float4*)(v + (size_t)idx[j] * DIM + lane * 8);
        float4 v0 = vr[0], v1 = vr[1];
        o0.x += wj * v0.x; o0.y += wj * v0.y; o0.z += wj * v0.z; o0.w += wj * v0.w;
        o1.x += wj * v1.x; o1.y += wj * v1.y; o1.z += wj * v1.z; o1.w += wj * v1.w;
    }
    float4* orow = (float4*)(out + (size_t)n * DIM + lane * 8);
    orow[0] = o0; orow[1] = o1;
}

// ---------------- launch ---------------------------------------------------
extern "C" void kernel_launch(void* const* d_in, const int* in_sizes, int n_in,
                              void* d_out, int out_size) {
    const float* x     = (const float*)d_in[0];
    const float* pos   = (const float*)d_in[1];
    const float* ln1_w = (const float*)d_in[2];
    const float* ln1_b = (const float*)d_in[3];
    const float* Wq    = (const float*)d_in[4];
    const float* bq    = (const float*)d_in[5];
    const float* Wk    = (const float*)d_in[6];
    const float* bk    = (const float*)d_in[7];
    const float* Wv    = (const float*)d_in[8];
    const float* bv    = (const float*)d_in[9];
    const float* Wo    = (const float*)d_in[10];
    const float* bo    = (const float*)d_in[11];
    const float* ln2_w = (const float*)d_in[12];
    const float* ln2_b = (const float*)d_in[13];
    const float* W1    = (const float*)d_in[14];
    const float* b1    = (const float*)d_in[15];
    const float* W2    = (const float*)d_in[16];
    const float* b2    = (const float*)d_in[17];
    float* out = (float*)d_out;

    void* p;
    cudaGetSymbolAddress(&p, g_h);    float* h    = (float*)p;
    cudaGetSymbolAddress(&p, g_q);    float* qb   = (float*)p;
    cudaGetSymbolAddress(&p, g_k);    float* kb   = (float*)p;
    cudaGetSymbolAddress(&p, g_v);    float* vb   = (float*)p;
    cudaGetSymbolAddress(&p, g_attn); float* ab   = (float*)p;
    cudaGetSymbolAddress(&p, g_x1);   float* x1   = (float*)p;
    cudaGetSymbolAddress(&p, g_hid);  float* hid  = (float*)p;
    cudaGetSymbolAddress(&p, g_knn);  int*   knn  = (int*)p;

    // kNN graph (independent of feature path; launch first)
    knn_part_kernel<<<dim3(N_PTS / 256, SEGS), 256>>>(pos);
    knn_merge_kernel<<<N_PTS / 256, 256>>>();

    // h = LN1(x)
    ln_kernel<<<N_PTS / 8, 256>>>(x, ln1_w, ln1_b, h);

    // q/k/v projections
    dim3 gqkv(DIM / BN, N_PTS / BM);
    gemm_kernel<0, 0><<<gqkv, 256>>>(h, Wq, bq, nullptr, qb, N_PTS, DIM, DIM);
    gemm_kernel<0, 0><<<gqkv, 256>>>(h, Wk, bk, nullptr, kb, N_PTS, DIM, DIM);
    gemm_kernel<0, 0><<<gqkv, 256>>>(h, Wv, bv, nullptr, vb, N_PTS, DIM, DIM);

    // local attention over kNN
    attn_kernel<<<N_PTS / 8, 256>>>(qb, kb, vb, knn, ab);

    // x1 = x + attn @ Wo^T + bo
    gemm_kernel<0, 1><<<gqkv, 256>>>(ab, Wo, bo, x, x1, N_PTS, DIM, DIM);

    // h2 = LN2(x1)  (reuse h)
    ln_kernel<<<N_PTS / 8, 256>>>(x1, ln2_w, ln2_b, h);

    // hid = gelu(h2 @ W1^T + b1)
    gemm_kernel<1, 0><<<dim3(MLP_HID / BN, N_PTS / BM), 256>>>(h, W1, b1, nullptr, hid,
                                                               N_PTS, MLP_HID, DIM);
    // out = x1 + hid @ W2^T + b2
    gemm_kernel<0, 1><<<gqkv, 256>>>(hid, W2, b2, x1, out, N_PTS, DIM, MLP_HID);
}

// round 2
// speedup vs baseline: 1.8558x; 1.8558x over previous
#include <cuda_runtime.h>
#include <math.h>

#define N_PTS 16384
#define DIM 256
#define HEADS 8
#define HD 32
#define KNN 20
#define MLP_HID 1024
#define SCALE 0.17677669529663687f  // 32^-0.5
#define FULLMASK 0xffffffffu
#define KTILE 1024                  // candidates staged per smem tile

// ---------------- scratch (device globals; no allocation allowed) ----------
__device__ float g_h[N_PTS * DIM];       // LN1 out, later reused for LN2 out
__device__ float g_q[N_PTS * DIM];
__device__ float g_k[N_PTS * DIM];
__device__ float g_v[N_PTS * DIM];
__device__ float g_attn[N_PTS * DIM];
__device__ float g_x1[N_PTS * DIM];      // residual-1 result
__device__ float g_hid[N_PTS * MLP_HID];
__device__ int   g_knn[N_PTS * KNN];
__device__ float4 g_pos4[N_PTS];

// ---------------- pack positions into float4 for LDS.128 -------------------
__global__ __launch_bounds__(256) void pack_pos_kernel(const float* __restrict__ pos) {
    const int i = blockIdx.x * blockDim.x + threadIdx.x;
    float4 p;
    p.x = pos[i * 3 + 0];
    p.y = pos[i * 3 + 1];
    p.z = pos[i * 3 + 2];
    p.w = 0.0f;
    g_pos4[i] = p;
}

// ---------------- kNN: one warp per query, lane-distributed top-21 ---------
// Lane j (0..20) holds the j-th smallest (d, idx); lanes 21..31 hold +inf.
// Insert is a parallel ballot/popc/shfl_up shift — O(1) warp work per insert.
__global__ __launch_bounds__(256) void knn_warp_kernel() {
    __shared__ float4 tile[KTILE];
    const int lane = threadIdx.x & 31;
    const int warp = threadIdx.x >> 5;
    const int qi = blockIdx.x * 8 + warp;

    const float4 qp = g_pos4[qi];

    float list_d = 3.0e38f;
    int   list_i = -1;
    float tau = 3.0e38f;

    for (int base = 0; base < N_PTS; base += KTILE) {
        __syncthreads();
        for (int t = threadIdx.x; t < KTILE; t += 256)
            tile[t] = g_pos4[base + t];
        __syncthreads();

#pragma unroll 4
        for (int s = 0; s < KTILE / 32; s++) {
            const float4 c = tile[s * 32 + lane];
            const int cidx = base + s * 32 + lane;
            const float dx = qp.x - c.x;
            const float dy = qp.y - c.y;
            const float dz = qp.z - c.z;
            const float d = dx * dx + dy * dy + dz * dz;

            unsigned m = __ballot_sync(FULLMASK, d < tau);
            while (m) {
                const int src = __ffs(m) - 1;
                m &= m - 1;
                const float d_new = __shfl_sync(FULLMASK, d, src);
                const int   i_new = __shfl_sync(FULLMASK, cidx, src);
                if (d_new < tau) {  // uniform recheck against updated tau
                    // stable position: count of entries <= d_new
                    const unsigned leq = __ballot_sync(FULLMASK, list_d <= d_new);
                    const int pos = __popc(leq);
                    const float d_up = __shfl_up_sync(FULLMASK, list_d, 1);
                    const int   i_up = __shfl_up_sync(FULLMASK, list_i, 1);
                    if (lane > pos)      { list_d = d_up;  list_i = i_up;  }
                    else if (lane == pos){ list_d = d_new; list_i = i_new; }
                    if (lane > 20)       { list_d = 3.0e38f; list_i = -1;  }
                    tau = __shfl_sync(FULLMASK, list_d, 20);
                }
            }
        }
    }
    // rank 0 is self (d = 0); write ranks 1..20
    if (lane >= 1 && lane <= 20)
        g_knn[qi * KNN + (lane - 1)] = list_i;
}

// ---------------- LayerNorm: one warp per row ------------------------------
__global__ __launch_bounds__(256) void ln_kernel(const float* __restrict__ x,
                                                 const float* __restrict__ w,
                                                 const float* __restrict__ b,
                                                 float* __restrict__ out) {
    const int warp = threadIdx.x >> 5;
    const int lane = threadIdx.x & 31;
    const int n = blockIdx.x * 8 + warp;
    const float4* xr = (const float4*)(x + (size_t)n * DIM + lane * 8);
    float4 a0 = xr[0], a1 = xr[1];
    float s1 = a0.x + a0.y + a0.z + a0.w + a1.x + a1.y + a1.z + a1.w;
    float s2 = a0.x * a0.x + a0.y * a0.y + a0.z * a0.z + a0.w * a0.w +
               a1.x * a1.x + a1.y * a1.y + a1.z * a1.z + a1.w * a1.w;
#pragma unroll
    for (int off = 16; off > 0; off >>= 1) {
        s1 += __shfl_xor_sync(0xffffffffu, s1, off);
        s2 += __shfl_xor_sync(0xffffffffu, s2, off);
    }
    float m = s1 * (1.0f / DIM);
    float var = s2 * (1.0f / DIM) - m * m;
    float r = rsqrtf(var + 1e-5f);
    const float4* wr = (const float4*)(w + lane * 8);
    const float4* br = (const float4*)(b + lane * 8);
    float4 w0 = wr[0], w1 = wr[1], b0 = br[0], b1 = br[1];
    float4 o0, o1;
    o0.x = (a0.x - m) * r * w0.x + b0.x;
    o0.y = (a0.y - m) * r * w0.y + b0.y;
    o0.z = (a0.z - m) * r * w0.z + b0.z;
    o0.w = (a0.w - m) * r * w0.w + b0.w;
    o1.x = (a1.x - m) * r * w1.x + b1.x;
    o1.y = (a1.y - m) * r * w1.y + b1.y;
    o1.z = (a1.z - m) * r * w1.z + b1.z;
    o1.w = (a1.w - m) * r * w1.w + b1.w;
    float4* orow = (float4*)(out + (size_t)n * DIM + lane * 8);
    orow[0] = o0; orow[1] = o1;
}

// ---------------- generic SGEMM: C = act(A * B^T + bias) [+ R] -------------
// A [M,Kd] row-major, B [Nn,Kd] row-major (weight layout), C [M,Nn]
#define BM 64
#define BN 64
#define BKK 16

template <int ACT, int RES>
__global__ __launch_bounds__(256) void gemm_kernel(const float* __restrict__ A,
                                                   const float* __restrict__ B,
                                                   const float* __restrict__ bias,
                                                   const float* __restrict__ R,
                                                   float* __restrict__ C,
                                                   int M, int Nn, int Kd) {
    __shared__ float As[BKK][BM + 4];
    __shared__ float Bs[BKK][BN + 4];
    const int tid = threadIdx.x;
    const int n0 = blockIdx.x * BN;
    const int m0 = blockIdx.y * BM;
    const int lrow = tid >> 2;
    const int lcol = (tid & 3) * 4;
    const int ty = tid >> 4;
    const int tx = tid & 15;
    float acc[4][4] = {};
    for (int k0 = 0; k0 < Kd; k0 += BKK) {
        float4 av = *(const float4*)(A + (size_t)(m0 + lrow) * Kd + k0 + lcol);
        float4 bv = *(const float4*)(B + (size_t)(n0 + lrow) * Kd + k0 + lcol);
        As[lcol + 0][lrow] = av.x; As[lcol + 1][lrow] = av.y;
        As[lcol + 2][lrow] = av.z; As[lcol + 3][lrow] = av.w;
        Bs[lcol + 0][lrow] = bv.x; Bs[lcol + 1][lrow] = bv.y;
        Bs[lcol + 2][lrow] = bv.z; Bs[lcol + 3][lrow] = bv.w;
        __syncthreads();
#pragma unroll
        for (int kk = 0; kk < BKK; kk++) {
            float4 a = *(const float4*)&As[kk][ty * 4];
            float4 b = *(const float4*)&Bs[kk][tx * 4];
            acc[0][0] += a.x * b.x; acc[0][1] += a.x * b.y; acc[0][2] += a.x * b.z; acc[0][3] += a.x * b.w;
            acc[1][0] += a.y * b.x; acc[1][1] += a.y * b.y; acc[1][2] += a.y * b.z; acc[1][3] += a.y * b.w;
            acc[2][0] += a.z * b.x; acc[2][1] += a.z * b.y; acc[2][2] += a.z * b.z; acc[2][3] += a.z * b.w;
            acc[3][0] += a.w * b.x; acc[3][1] += a.w * b.y; acc[3][2] += a.w * b.z; acc[3][3] += a.w * b.w;
        }
        __syncthreads();
    }
    float4 bb = *(const float4*)(bias + n0 + tx * 4);
#pragma unroll
    for (int i = 0; i < 4; i++) {
        const int m = m0 + ty * 4 + i;
        float4 c;
        c.x = acc[i][0] + bb.x;
        c.y = acc[i][1] + bb.y;
        c.z = acc[i][2] + bb.z;
        c.w = acc[i][3] + bb.w;
        if (ACT == 1) {  // exact GELU
            c.x = 0.5f * c.x * (1.0f + erff(c.x * 0.70710678118654752f));
            c.y = 0.5f * c.y * (1.0f + erff(c.y * 0.70710678118654752f));
            c.z = 0.5f * c.z * (1.0f + erff(c.z * 0.70710678118654752f));
            c.w = 0.5f * c.w * (1.0f + erff(c.w * 0.70710678118654752f));
        }
        if (RES) {
            float4 r = *(const float4*)(R + (size_t)m * Nn + n0 + tx * 4);
            c.x += r.x; c.y += r.y; c.z += r.z; c.w += r.w;
        }
        *(float4*)(C + (size_t)m * Nn + n0 + tx * 4) = c;
    }
}

// ---------------- local attention: one warp per point ----------------------
// lane l handles feature elems [8l, 8l+8) => head = l/4, 4 lanes per head
__global__ __launch_bounds__(256) void attn_kernel(const float* __restrict__ q,
                                                   const float* __restrict__ k,
                                                   const float* __restrict__ v,
                                                   const int* __restrict__ knn,
                                                   float* __restrict__ out) {
    const int warp = threadIdx.x >> 5;
    const int lane = threadIdx.x & 31;
    const int n = blockIdx.x * 8 + warp;
    const float4* qr = (const float4*)(q + (size_t)n * DIM + lane * 8);
    float4 q0 = qr[0], q1 = qr[1];

    int idx[KNN];
#pragma unroll
    for (int j = 0; j < KNN; j++) idx[j] = knn[n * KNN + j];

    float w[KNN];
#pragma unroll
    for (int j = 0; j < KNN; j++) {
        const float4* kr = (const float4*)(k + (size_t)idx[j] * DIM + lane * 8);
        float4 k0 = kr[0], k1 = kr[1];
        float s = q0.x * k0.x + q0.y * k0.y + q0.z * k0.z + q0.w * k0.w +
                  q1.x * k1.x + q1.y * k1.y + q1.z * k1.z + q1.w * k1.w;
        s += __shfl_xor_sync(0xffffffffu, s, 1);
        s += __shfl_xor_sync(0xffffffffu, s, 2);
        w[j] = s * SCALE;
    }
    float mx = -3.0e38f;
#pragma unroll
    for (int j = 0; j < KNN; j++) mx = fmaxf(mx, w[j]);
    float sum = 0.0f;
#pragma unroll
    for (int j = 0; j < KNN; j++) { w[j] = expf(w[j] - mx); sum += w[j]; }
    const float inv = 1.0f / sum;

    float4 o0 = {0, 0, 0, 0}, o1 = {0, 0, 0, 0};
#pragma unroll
    for (int j = 0; j < KNN; j++) {
        const float wj = w[j] * inv;
        const float4* vr = (const float4*)(v + (size_t)idx[j] * DIM + lane * 8);
        float4 v0 = vr[0], v1 = vr[1];
        o0.x += wj * v0.x; o0.y += wj * v0.y; o0.z += wj * v0.z; o0.w += wj * v0.w;
        o1.x += wj * v1.x; o1.y += wj * v1.y; o1.z += wj * v1.z; o1.w += wj * v1.w;
    }
    float4* orow = (float4*)(out + (size_t)n * DIM + lane * 8);
    orow[0] = o0; orow[1] = o1;
}

// ---------------- launch ---------------------------------------------------
extern "C" void kernel_launch(void* const* d_in, const int* in_sizes, int n_in,
                              void* d_out, int out_size) {
    const float* x     = (const float*)d_in[0];
    const float* pos   = (const float*)d_in[1];
    const float* ln1_w = (const float*)d_in[2];
    const float* ln1_b = (const float*)d_in[3];
    const float* Wq    = (const float*)d_in[4];
    const float* bq    = (const float*)d_in[5];
    const float* Wk    = (const float*)d_in[6];
    const float* bk    = (const float*)d_in[7];
    const float* Wv    = (const float*)d_in[8];
    const float* bv    = (const float*)d_in[9];
    const float* Wo    = (const float*)d_in[10];
    const float* bo    = (const float*)d_in[11];
    const float* ln2_w = (const float*)d_in[12];
    const float* ln2_b = (const float*)d_in[13];
    const float* W1    = (const float*)d_in[14];
    const float* b1    = (const float*)d_in[15];
    const float* W2    = (const float*)d_in[16];
    const float* b2    = (const float*)d_in[17];
    float* out = (float*)d_out;

    void* p;
    cudaGetSymbolAddress(&p, g_h);    float* h    = (float*)p;
    cudaGetSymbolAddress(&p, g_q);    float* qb   = (float*)p;
    cudaGetSymbolAddress(&p, g_k);    float* kb   = (float*)p;
    cudaGetSymbolAddress(&p, g_v);    float* vb   = (float*)p;
    cudaGetSymbolAddress(&p, g_attn); float* ab   = (float*)p;
    cudaGetSymbolAddress(&p, g_x1);   float* x1   = (float*)p;
    cudaGetSymbolAddress(&p, g_hid);  float* hid  = (float*)p;
    cudaGetSymbolAddress(&p, g_knn);  int*   knn  = (int*)p;

    // kNN graph (independent of feature path; launch first)
    pack_pos_kernel<<<N_PTS / 256, 256>>>(pos);
    knn_warp_kernel<<<N_PTS / 8, 256>>>();

    // h = LN1(x)
    ln_kernel<<<N_PTS / 8, 256>>>(x, ln1_w, ln1_b, h);

    // q/k/v projections
    dim3 gqkv(DIM / BN, N_PTS / BM);
    gemm_kernel<0, 0><<<gqkv, 256>>>(h, Wq, bq, nullptr, qb, N_PTS, DIM, DIM);
    gemm_kernel<0, 0><<<gqkv, 256>>>(h, Wk, bk, nullptr, kb, N_PTS, DIM, DIM);
    gemm_kernel<0, 0><<<gqkv, 256>>>(h, Wv, bv, nullptr, vb, N_PTS, DIM, DIM);

    // local attention over kNN
    attn_kernel<<<N_PTS / 8, 256>>>(qb, kb, vb, knn, ab);

    // x1 = x + attn @ Wo^T + bo
    gemm_kernel<0, 1><<<gqkv, 256>>>(ab, Wo, bo, x, x1, N_PTS, DIM, DIM);

    // h2 = LN2(x1)  (reuse h)
    ln_kernel<<<N_PTS / 8, 256>>>(x1, ln2_w, ln2_b, h);

    // hid = gelu(h2 @ W1^T + b1)
    gemm_kernel<1, 0><<<dim3(MLP_HID / BN, N_PTS / BM), 256>>>(h, W1, b1, nullptr, hid,
                                                               N_PTS, MLP_HID, DIM);
    // out = x1 + hid @ W2^T + b2
    gemm_kernel<0, 1><<<gqkv, 256>>>(hid, W2, b2, x1, out, N_PTS, DIM, MLP_HID);
}

// round 4
// speedup vs baseline: 3.2702x; 1.7621x over previous
#include <cuda_runtime.h>
#include <math.h>
#include <cstdint>

#define N_PTS 16384
#define DIM 256
#define HEADS 8
#define HD 32
#define KNN 20
#define MLP_HID 1024
#define SCALE 0.17677669529663687f  // 32^-0.5
#define FULLMASK 0xffffffffu
#define KTILE 1024                  // kNN candidates staged per smem tile

// ---------------- scratch (device globals; no allocation allowed) ----------
__device__ float g_h[N_PTS * DIM];       // LN1 out, later reused for LN2 out
__device__ float g_q[N_PTS * DIM];
__device__ float g_k[N_PTS * DIM];
__device__ float g_v[N_PTS * DIM];
__device__ float g_attn[N_PTS * DIM];
__device__ float g_x1[N_PTS * DIM];      // residual-1 result
__device__ float g_hid[N_PTS * MLP_HID];
__device__ int   g_knn[N_PTS * KNN];
__device__ float4 g_pos4[N_PTS];

// ---------------- tf32 helpers ---------------------------------------------
__device__ __forceinline__ float to_tf32(float x) {
    float r;
    asm("cvt.rna.tf32.f32 %0, %1;" : "=f"(r) : "f"(x));
    return r;
}

__device__ __forceinline__ void mma_tf32(float* c, const uint32_t* a, const uint32_t* b) {
    asm volatile(
        "mma.sync.aligned.m16n8k8.row.col.f32.tf32.tf32.f32 "
        "{%0,%1,%2,%3}, {%4,%5,%6,%7}, {%8,%9}, {%0,%1,%2,%3};"
        : "+f"(c[0]), "+f"(c[1]), "+f"(c[2]), "+f"(c[3])
        : "r"(a[0]), "r"(a[1]), "r"(a[2]), "r"(a[3]), "r"(b[0]), "r"(b[1]));
}

// ==================== tf32 mma.sync GEMM ====================
// C[M,Nn] = act(A[M,Kd] * B[Nn,Kd]^T + bias) [+ R]
// CTA tile 128x128, 8 warps (4m x 2n), warp tile 32x64, K chunk 32.
#define SK 36   // smem row stride (floats): banks (4m+k)%32 all-distinct

template <int ACT, int RES>
__global__ __launch_bounds__(256) void tc_gemm(const float* __restrict__ A,
                                               const float* __restrict__ B,
                                               const float* __restrict__ bias,
                                               const float* __restrict__ R,
                                               float* __restrict__ C,
                                               int M, int Nn, int Kd) {
    __shared__ float As[128 * SK];
    __shared__ float Bs[128 * SK];

    const int tid = threadIdx.x;
    const int wid = tid >> 5;
    const int lane = tid & 31;
    const int g = lane >> 2;     // groupID   0..7
    const int t = lane & 3;      // tid-in-group 0..3
    const int m0 = blockIdx.y * 128;
    const int n0 = blockIdx.x * 128;
    const int wm = (wid >> 1) * 32;   // warp m offset (4 warps)
    const int wn = (wid & 1) * 64;    // warp n offset (2 warps)

    float acc[2][8][4];
#pragma unroll
    for (int mt = 0; mt < 2; mt++)
#pragma unroll
        for (int nt = 0; nt < 8; nt++)
#pragma unroll
            for (int j = 0; j < 4; j++) acc[mt][nt][j] = 0.0f;

    // staging coords: each thread loads 16 floats of A and of B per chunk
    const int srow = tid >> 1;           // 0..127
    const int skq  = (tid & 1) * 16;     // 0 or 16

    for (int k0 = 0; k0 < Kd; k0 += 32) {
        const float* ag = A + (size_t)(m0 + srow) * Kd + k0 + skq;
        const float* bg = B + (size_t)(n0 + srow) * Kd + k0 + skq;
        float* as = As + srow * SK + skq;
        float* bs = Bs + srow * SK + skq;
#pragma unroll
        for (int j = 0; j < 4; j++) {
            float4 va = *(const float4*)(ag + j * 4);
            float4 vb = *(const float4*)(bg + j * 4);
            as[j * 4 + 0] = to_tf32(va.x); as[j * 4 + 1] = to_tf32(va.y);
            as[j * 4 + 2] = to_tf32(va.z); as[j * 4 + 3] = to_tf32(va.w);
            bs[j * 4 + 0] = to_tf32(vb.x); bs[j * 4 + 1] = to_tf32(vb.y);
            bs[j * 4 + 2] = to_tf32(vb.z); bs[j * 4 + 3] = to_tf32(vb.w);
        }
        __syncthreads();

#pragma unroll
        for (int ks = 0; ks < 4; ks++) {
            const int kk = ks * 8;
            uint32_t a[2][4];
#pragma unroll
            for (int mt = 0; mt < 2; mt++) {
                const float* ap = As + (wm + mt * 16 + g) * SK + kk + t;
                a[mt][0] = __float_as_uint(ap[0]);
                a[mt][1] = __float_as_uint(ap[8 * SK]);
                a[mt][2] = __float_as_uint(ap[4]);
                a[mt][3] = __float_as_uint(ap[8 * SK + 4]);
            }
            uint32_t b[8][2];
#pragma unroll
            for (int nt = 0; nt < 8; nt++) {
                const float* bp = Bs + (wn + nt * 8 + g) * SK + kk + t;
                b[nt][0] = __float_as_uint(bp[0]);
                b[nt][1] = __float_as_uint(bp[4]);
            }
#pragma unroll
            for (int mt = 0; mt < 2; mt++)
#pragma unroll
                for (int nt = 0; nt < 8; nt++)
                    mma_tf32(acc[mt][nt], a[mt], b[nt]);
        }
        __syncthreads();
    }

    // epilogue: D[g + mt*16 (+8)][2t, 2t+1] per nt tile
#pragma unroll
    for (int mt = 0; mt < 2; mt++) {
#pragma unroll
        for (int half = 0; half < 2; half++) {
            const int m = m0 + wm + mt * 16 + g + half * 8;
            float* crow = C + (size_t)m * Nn + n0 + wn;
            const float* rrow = R + (size_t)m * Nn + n0 + wn;
#pragma unroll
            for (int nt = 0; nt < 8; nt++) {
                const int nc = nt * 8 + 2 * t;
                float2 c;
                c.x = acc[mt][nt][half * 2 + 0] + bias[n0 + wn + nc + 0];
                c.y = acc[mt][nt][half * 2 + 1] + bias[n0 + wn + nc + 1];
                if (ACT == 1) {  // exact GELU
                    c.x = 0.5f * c.x * (1.0f + erff(c.x * 0.70710678118654752f));
                    c.y = 0.5f * c.y * (1.0f + erff(c.y * 0.70710678118654752f));
                }
                if (RES) {
                    c.x += rrow[nc + 0];
                    c.y += rrow[nc + 1];
                }
                *(float2*)(crow + nc) = c;
            }
        }
    }
}

// ---------------- pack positions into float4 for LDS.128 -------------------
__global__ __launch_bounds__(256) void pack_pos_kernel(const float* __restrict__ pos) {
    const int i = blockIdx.x * blockDim.x + threadIdx.x;
    float4 p;
    p.x = pos[i * 3 + 0];
    p.y = pos[i * 3 + 1];
    p.z = pos[i * 3 + 2];
    p.w = 0.0f;
    g_pos4[i] = p;
}

// ---------------- kNN: one warp per query, lane-distributed top-21 ---------
__global__ __launch_bounds__(256) void knn_warp_kernel() {
    __shared__ float4 tile[KTILE];
    const int lane = threadIdx.x & 31;
    const int warp = threadIdx.x >> 5;
    const int qi = blockIdx.x * 8 + warp;

    const float4 qp = g_pos4[qi];

    float list_d = 3.0e38f;
    int   list_i = -1;
    float tau = 3.0e38f;

    for (int base = 0; base < N_PTS; base += KTILE) {
        __syncthreads();
        for (int tt = threadIdx.x; tt < KTILE; tt += 256)
            tile[tt] = g_pos4[base + tt];
        __syncthreads();

#pragma unroll 4
        for (int s = 0; s < KTILE / 32; s++) {
            const float4 c = tile[s * 32 + lane];
            const int cidx = base + s * 32 + lane;
            const float dx = qp.x - c.x;
            const float dy = qp.y - c.y;
            const float dz = qp.z - c.z;
            const float d = dx * dx + dy * dy + dz * dz;

            unsigned m = __ballot_sync(FULLMASK, d < tau);
            while (m) {
                const int src = __ffs(m) - 1;
                m &= m - 1;
                const float d_new = __shfl_sync(FULLMASK, d, src);
                const int   i_new = __shfl_sync(FULLMASK, cidx, src);
                if (d_new < tau) {
                    const unsigned leq = __ballot_sync(FULLMASK, list_d <= d_new);
                    const int pos = __popc(leq);
                    const float d_up = __shfl_up_sync(FULLMASK, list_d, 1);
                    const int   i_up = __shfl_up_sync(FULLMASK, list_i, 1);
                    if (lane > pos)       { list_d = d_up;  list_i = i_up;  }
                    else if (lane == pos) { list_d = d_new; list_i = i_new; }
                    if (lane > 20)        { list_d = 3.0e38f; list_i = -1;  }
                    tau = __shfl_sync(FULLMASK, list_d, 20);
                }
            }
        }
    }
    if (lane >= 1 && lane <= 20)
        g_knn[qi * KNN + (lane - 1)] = list_i;
}

// ---------------- LayerNorm: one warp per row ------------------------------
__global__ __launch_bounds__(256) void ln_kernel(const float* __restrict__ x,
                                                 const float* __restrict__ w,
                                                 const float* __restrict__ b,
                                                 float* __restrict__ out) {
    const int warp = threadIdx.x >> 5;
    const int lane = threadIdx.x & 31;
    const int n = blockIdx.x * 8 + warp;
    const float4* xr = (const float4*)(x + (size_t)n * DIM + lane * 8);
    float4 a0 = xr[0], a1 = xr[1];
    float s1 = a0.x + a0.y + a0.z + a0.w + a1.x + a1.y + a1.z + a1.w;
    float s2 = a0.x * a0.x + a0.y * a0.y + a0.z * a0.z + a0.w * a0.w +
               a1.x * a1.x + a1.y * a1.y + a1.z * a1.z + a1.w * a1.w;
#pragma unroll
    for (int off = 16; off > 0; off >>= 1) {
        s1 += __shfl_xor_sync(0xffffffffu, s1, off);
        s2 += __shfl_xor_sync(0xffffffffu, s2, off);
    }
    float m = s1 * (1.0f / DIM);
    float var = s2 * (1.0f / DIM) - m * m;
    float r = rsqrtf(var + 1e-5f);
    const float4* wr = (const float4*)(w + lane * 8);
    const float4* br = (const float4*)(b + lane * 8);
    float4 w0 = wr[0], w1 = wr[1], b0 = br[0], b1 = br[1];
    float4 o0, o1;
    o0.x = (a0.x - m) * r * w0.x + b0.x;
    o0.y = (a0.y - m) * r * w0.y + b0.y;
    o0.z = (a0.z - m) * r * w0.z + b0.z;
    o0.w = (a0.w - m) * r * w0.w + b0.w;
    o1.x = (a1.x - m) * r * w1.x + b1.x;
    o1.y = (a1.y - m) * r * w1.y + b1.y;
    o1.z = (a1.z - m) * r * w1.z + b1.z;
    o1.w = (a1.w - m) * r * w1.w + b1.w;
    float4* orow = (float4*)(out + (size_t)n * DIM + lane * 8);
    orow[0] = o0; orow[1] = o1;
}

// ---------------- local attention: one warp per point ----------------------
__global__ __launch_bounds__(256) void attn_kernel(const float* __restrict__ q,
                                                   const float* __restrict__ k,
                                                   const float* __restrict__ v,
                                                   const int* __restrict__ knn,
                                                   float* __restrict__ out) {
    const int warp = threadIdx.x >> 5;
    const int lane = threadIdx.x & 31;
    const int n = blockIdx.x * 8 + warp;
    const float4* qr = (const float4*)(q + (size_t)n * DIM + lane * 8);
    float4 q0 = qr[0], q1 = qr[1];

    int idx[KNN];
#pragma unroll
    for (int j = 0; j < KNN; j++) idx[j] = knn[n * KNN + j];

    float w[KNN];
#pragma unroll
    for (int j = 0; j < KNN; j++) {
        const float4* kr = (const float4*)(k + (size_t)idx[j] * DIM + lane * 8);
        float4 k0 = kr[0], k1 = kr[1];
        float s = q0.x * k0.x + q0.y * k0.y + q0.z * k0.z + q0.w * k0.w +
                  q1.x * k1.x + q1.y * k1.y + q1.z * k1.z + q1.w * k1.w;
        s += __shfl_xor_sync(0xffffffffu, s, 1);
        s += __shfl_xor_sync(0xffffffffu, s, 2);
        w[j] = s * SCALE;
    }
    float mx = -3.0e38f;
#pragma unroll
    for (int j = 0; j < KNN; j++) mx = fmaxf(mx, w[j]);
    float sum = 0.0f;
#pragma unroll
    for (int j = 0; j < KNN; j++) { w[j] = expf(w[j] - mx); sum += w[j]; }
    const float inv = 1.0f / sum;

    float4 o0 = {0, 0, 0, 0}, o1 = {0, 0, 0, 0};
#pragma unroll
    for (int j = 0; j < KNN; j++) {
        const float wj = w[j] * inv;
        const float4* vr = (const float4*)(v + (size_t)idx[j] * DIM + lane * 8);
        float4 v0 = vr[0], v1 = vr[1];
        o0.x += wj * v0.x; o0.y += wj * v0.y; o0.z += wj * v0.z; o0.w += wj * v0.w;
        o1.x += wj * v1.x; o1.y += wj * v1.y; o1.z += wj * v1.z; o1.w += wj * v1.w;
    }
    float4* orow = (float4*)(out + (size_t)n * DIM + lane * 8);
    orow[0] = o0; orow[1] = o1;
}

// ---------------- launch ---------------------------------------------------
extern "C" void kernel_launch(void* const* d_in, const int* in_sizes, int n_in,
                              void* d_out, int out_size) {
    const float* x     = (const float*)d_in[0];
    const float* pos   = (const float*)d_in[1];
    const float* ln1_w = (const float*)d_in[2];
    const float* ln1_b = (const float*)d_in[3];
    const float* Wq    = (const float*)d_in[4];
    const float* bq    = (const float*)d_in[5];
    const float* Wk    = (const float*)d_in[6];
    const float* bk    = (const float*)d_in[7];
    const float* Wv    = (const float*)d_in[8];
    const float* bv    = (const float*)d_in[9];
    const float* Wo    = (const float*)d_in[10];
    const float* bo    = (const float*)d_in[11];
    const float* ln2_w = (const float*)d_in[12];
    const float* ln2_b = (const float*)d_in[13];
    const float* W1    = (const float*)d_in[14];
    const float* b1    = (const float*)d_in[15];
    const float* W2    = (const float*)d_in[16];
    const float* b2    = (const float*)d_in[17];
    float* out = (float*)d_out;

    void* p;
    cudaGetSymbolAddress(&p, g_h);    float* h    = (float*)p;
    cudaGetSymbolAddress(&p, g_q);    float* qb   = (float*)p;
    cudaGetSymbolAddress(&p, g_k);    float* kb   = (float*)p;
    cudaGetSymbolAddress(&p, g_v);    float* vb   = (float*)p;
    cudaGetSymbolAddress(&p, g_attn); float* ab   = (float*)p;
    cudaGetSymbolAddress(&p, g_x1);   float* x1   = (float*)p;
    cudaGetSymbolAddress(&p, g_hid);  float* hid  = (float*)p;
    cudaGetSymbolAddress(&p, g_knn);  int*   knn  = (int*)p;

    // kNN graph (independent of feature path; launch first)
    pack_pos_kernel<<<N_PTS / 256, 256>>>(pos);
    knn_warp_kernel<<<N_PTS / 8, 256>>>();

    // h = LN1(x)
    ln_kernel<<<N_PTS / 8, 256>>>(x, ln1_w, ln1_b, h);

    // q/k/v projections (tf32 mma.sync)
    dim3 gqkv(DIM / 128, N_PTS / 128);
    tc_gemm<0, 0><<<gqkv, 256>>>(h, Wq, bq, nullptr, qb, N_PTS, DIM, DIM);
    tc_gemm<0, 0><<<gqkv, 256>>>(h, Wk, bk, nullptr, kb, N_PTS, DIM, DIM);
    tc_gemm<0, 0><<<gqkv, 256>>>(h, Wv, bv, nullptr, vb, N_PTS, DIM, DIM);

    // local attention over kNN
    attn_kernel<<<N_PTS / 8, 256>>>(qb, kb, vb, knn, ab);

    // x1 = x + attn @ Wo^T + bo
    tc_gemm<0, 1><<<gqkv, 256>>>(ab, Wo, bo, x, x1, N_PTS, DIM, DIM);

    // h2 = LN2(x1)  (reuse h)
    ln_kernel<<<N_PTS / 8, 256>>>(x1, ln2_w, ln2_b, h);

    // hid = gelu(h2 @ W1^T + b1)
    tc_gemm<1, 0><<<dim3(MLP_HID / 128, N_PTS / 128), 256>>>(h, W1, b1, nullptr, hid,
                                                             N_PTS, MLP_HID, DIM);
    // out = x1 + hid @ W2^T + b2
    tc_gemm<0, 1><<<gqkv, 256>>>(hid, W2, b2, x1, out, N_PTS, DIM, MLP_HID);
}